// round 13
// baseline (speedup 1.0000x reference)
#include <cuda_runtime.h>
#include <math.h>

#define HH 256
#define WW 704
#define HWP (HH*WW)          // 180224
#define HWP4 (HWP/4)         // 45056
#define W4  (WW/4)           // 176 float4 per row
#define CIMG 256
#define RPB 64               // rows per band
#define NBANDS 4
#define BAND_PG (RPB*W4)     // 11264 float4 pixel-groups per band

// ---------------- scratch (static device globals; no allocation) ----------------
__device__ __align__(16) float g_gated[HWP];
__device__ __align__(16) float g_L[HWP];
__device__ __align__(16) float g_att[HWP];
__device__ float g_t[9*131];
__device__ float g_swsum[9];
__device__ float g_gconst[9];
__device__ float g_const2[131];
__device__ __align__(16) float4 g_M4_0[9*8];    // FC=32
__device__ __align__(16) float4 g_M4_1[9*16];   // FC=64
__device__ __align__(16) float4 g_M4_2[9*32];   // FC=128
__device__ float g_C0[27], g_C1[27], g_C2[27];  // [d][3] coord weights

__device__ __forceinline__ float warp_red(float s) {
#pragma unroll
    for (int o = 16; o > 0; o >>= 1) s += __shfl_xor_sync(0xffffffffu, s, o);
    return s;
}

// ---------------- initA: zero L (176 float4 blocks) + warp-dot tasks ------------
#define ZB 176
#define NTA 1319
__global__ __launch_bounds__(256) void initA_kernel(
    const float* __restrict__ W2, const float* __restrict__ b2,
    const float* __restrict__ b0, const float* __restrict__ b1,
    const float* __restrict__ spw)
{
    int b = blockIdx.x;
    if (b < ZB) {
        reinterpret_cast<float4*>(g_L)[b*256 + threadIdx.x] = make_float4(0.f,0.f,0.f,0.f);
        return;
    }
    int task = (b - ZB)*8 + (threadIdx.x >> 5);
    int lane = threadIdx.x & 31;
    if (task >= NTA) return;

    if (task < 131) {
        int c = task;
        float s = 0.f;
        for (int k = lane; k < 131; k += 32) s += W2[c*131+k]*(b0[k]+b1[k]);
        s = warp_red(s);
        if (lane == 0) g_const2[c] = s + b2[c];
    } else if (task < 140) {
        int d = task - 131;
        float s = 0.f;
        for (int c = lane; c < 131; c += 32) s += spw[c*9+d];
        s = warp_red(s);
        if (lane == 0) g_swsum[d] = s;
    } else {
        int idx = task - 140;
        int d = idx / 131, k = idx - d*131;
        float s = 0.f;
        for (int c = lane; c < 131; c += 32) s += spw[c*9+d]*W2[c*131+k];
        s = warp_red(s);
        if (lane == 0) g_t[idx] = s;
    }
}

// ---------------- initB: gconst + M0/M1 (packed) + pack t -----------------------
#define NTB 927
#define NBB ((NTB + 7)/8)       // 116
__global__ __launch_bounds__(256) void initB_kernel(
    const float* __restrict__ W0, const float* __restrict__ W1,
    const float* __restrict__ spw)
{
    int b = blockIdx.x;
    if (b == NBB) {  // pack t -> M4_2 / C2
        for (int i = threadIdx.x; i < 9*131; i += 256) {
            int d = i / 131, j = i - d*131;
            float v = g_t[i];
            if (j < 128) reinterpret_cast<float*>(g_M4_2)[d*128 + j] = v;
            else         g_C2[d*3 + (j - 128)] = v;
        }
        return;
    }
    int task = b*8 + (threadIdx.x >> 5);
    int lane = threadIdx.x & 31;
    if (task >= NTB) return;

    if (task < 9) {
        int d = task;
        float s = 0.f;
        for (int c = lane; c < 131; c += 32) s += spw[c*9+d]*g_const2[c];
        s = warp_red(s);
        if (lane == 0) g_gconst[d] = s;
    } else if (task < 324) {
        int idx = task - 9;
        int d = idx / 35, j = idx - d*35;
        float s = 0.f;
        for (int k = lane; k < 131; k += 32) s += g_t[d*131+k]*W0[k*35+j];
        s = warp_red(s);
        if (lane == 0) {
            if (j < 32) reinterpret_cast<float*>(g_M4_0)[d*32 + j] = s;
            else        g_C0[d*3 + (j - 32)] = s;
        }
    } else {
        int idx = task - 324;
        int d = idx / 67, j = idx - d*67;
        float s = 0.f;
        for (int k = lane; k < 131; k += 32) s += g_t[d*131+k]*W1[k*67+j];
        s = warp_red(s);
        if (lane == 0) {
            if (j < 64) reinterpret_cast<float*>(g_M4_1)[d*64 + j] = s;
            else        g_C1[d*3 + (j - 64)] = s;
        }
    }
}

// -------- quad-split scatter: 4 lanes per point, 128 points per block (2x64) ----
template<int FC>
__device__ __forceinline__ void scatter_body(const float* __restrict__ feat,
                                             const float* __restrict__ coord,
                                             const int*   __restrict__ grid,
                                             int N, const float4* __restrict__ M4g,
                                             const float* __restrict__ Cg, int blk,
                                             float4* sM4, float* sC)
{
    constexpr int K4 = FC/4;
    constexpr int IT = K4/4;
    const int tid = threadIdx.x;
    for (int i = tid; i < 9*K4; i += 256) sM4[i] = M4g[i];
    if (tid < 27) sC[tid] = Cg[tid];
    __syncthreads();

    const int lane = tid & 31;
    const int q    = lane >> 2;
    const int l    = lane & 3;

#pragma unroll
    for (int half = 0; half < 2; half++) {
        const int pt = blk*128 + half*64 + (tid >> 5)*8 + q;
        const bool valid = pt < N;

        float acc[9];
#pragma unroll
        for (int d = 0; d < 9; d++) acc[d] = 0.f;

        if (valid) {
            const float4* xf = reinterpret_cast<const float4*>(feat) + (size_t)pt*K4;
#pragma unroll
            for (int it = 0; it < IT; it++) {
                float4 x = xf[l + 4*it];
#pragma unroll
                for (int d = 0; d < 9; d++) {
                    float4 m = sM4[d*K4 + l + 4*it];
                    acc[d] += m.x*x.x + m.y*x.y + m.z*x.z + m.w*x.w;
                }
            }
        }
#pragma unroll
        for (int d = 0; d < 9; d++) {
            acc[d] += __shfl_xor_sync(0xffffffffu, acc[d], 1);
            acc[d] += __shfl_xor_sync(0xffffffffu, acc[d], 2);
        }
        if (valid && l == 0) {
            float c0 = coord[3*(size_t)pt+0], c1 = coord[3*(size_t)pt+1], c2 = coord[3*(size_t)pt+2];
            const int gx = grid[2*pt+0];
            const int gy = grid[2*pt+1];
#pragma unroll
            for (int d = 0; d < 9; d++) {
                float v = acc[d] + sC[d*3+0]*c0 + sC[d*3+1]*c1 + sC[d*3+2]*c2;
                int dy = d/3, dx = d - 3*dy;
                int pr = gy + 1 - dy, pc = gx + 1 - dx;
                if (pr >= 0 && pr < HH && pc >= 0 && pc < WW)
                    atomicAdd(&g_L[pr*WW + pc], v);
            }
        }
    }
}

// -------- gated body: 64-f4 unit, 4-way channel split, range-guarded ------------
__device__ __forceinline__ void gated_unit(const float* __restrict__ img,
                                           const float* __restrict__ w3,
                                           const float* __restrict__ b3,
                                           int p4_start, int p4_end, int unit,
                                           float* sw, float4* sPart)
{
    const int tid = threadIdx.x;
    for (int i = tid; i < CIMG; i += 256) sw[i] = w3[i];
    __syncthreads();
    const int f  = tid & 63;
    const int qq = tid >> 6;
    const int p4 = p4_start + unit*64 + f;
    const bool ok = p4 < p4_end;
    const float4* img4 = reinterpret_cast<const float4*>(img);
    float4 a0 = make_float4(0.f,0.f,0.f,0.f);
    float4 a1 = make_float4(0.f,0.f,0.f,0.f);
    if (ok) {
        const int cbase = qq*64;
#pragma unroll 8
        for (int c = cbase; c < cbase + 64; c += 2) {
            float4 v0 = img4[(size_t)c*HWP4 + p4];
            float4 v1 = img4[(size_t)(c+1)*HWP4 + p4];
            float w0 = sw[c], w1 = sw[c+1];
            a0.x += w0*v0.x; a0.y += w0*v0.y; a0.z += w0*v0.z; a0.w += w0*v0.w;
            a1.x += w1*v1.x; a1.y += w1*v1.y; a1.z += w1*v1.z; a1.w += w1*v1.w;
        }
    }
    a0.x += a1.x; a0.y += a1.y; a0.z += a1.z; a0.w += a1.w;
    sPart[tid] = a0;
    __syncthreads();
    if (ok && tid < 64) {
        float4 r0 = sPart[tid], r1 = sPart[tid+64], r2 = sPart[tid+128], r3 = sPart[tid+192];
        float bb = __ldg(b3);
        float4 r = make_float4(bb + r0.x + r1.x + r2.x + r3.x,
                               bb + r0.y + r1.y + r2.y + r3.y,
                               bb + r0.z + r1.z + r2.z + r3.z,
                               bb + r0.w + r1.w + r2.w + r3.w);
        reinterpret_cast<float4*>(g_gated)[p4] = r;
    }
}

// -------- fused0: gated band 0 (with halo) + ALL scatter blocks ------------------
__global__ __launch_bounds__(256, 8) void fused0_kernel(
    const float* __restrict__ img, const float* __restrict__ w3, const float* __restrict__ b3,
    int g_units, int p4_start, int p4_end,
    const float* __restrict__ f0, const float* __restrict__ c0, const int* __restrict__ gr0, int N0, int SB0,
    const float* __restrict__ f1, const float* __restrict__ c1, const int* __restrict__ gr1, int N1, int SB1,
    const float* __restrict__ f2, const float* __restrict__ c2, const int* __restrict__ gr2, int N2)
{
    __shared__ float  sw[CIMG];
    __shared__ float4 sPart[256];
    __shared__ float4 sM4[9*32];
    __shared__ float  sC[27];
    int b = blockIdx.x;

    if (b < g_units) { gated_unit(img, w3, b3, p4_start, p4_end, b, sw, sPart); return; }
    b -= g_units;
    if (b < SB0) { scatter_body<32>(f0, c0, gr0, N0, g_M4_0, g_C0, b, sM4, sC); return; }
    b -= SB0;
    if (b < SB1) { scatter_body<64>(f1, c1, gr1, N1, g_M4_1, g_C1, b, sM4, sC); return; }
    b -= SB1;
    scatter_body<128>(f2, c2, gr2, N2, g_M4_2, g_C2, b, sM4, sC);
}

// -------- gated band kernel (bands 1..3, with halo) ------------------------------
__global__ __launch_bounds__(256) void gated_band_kernel(
    const float* __restrict__ img, const float* __restrict__ w3, const float* __restrict__ b3,
    int p4_start, int p4_end)
{
    __shared__ float  sw[CIMG];
    __shared__ float4 sPart[256];
    gated_unit(img, w3, b3, p4_start, p4_end, blockIdx.x, sw, sPart);
}

// ---------------- attention band: sigmoid(spb + L + taps(gated) + consts) -------
__global__ __launch_bounds__(256) void attention_kernel(const float* __restrict__ spb,
                                                        int p_start)
{
    int p = p_start + blockIdx.x*256 + threadIdx.x;
    int r = p / WW, c = p - r*WW;
    float acc = __ldg(spb) + g_L[p];
#pragma unroll
    for (int d = 0; d < 9; d++) {
        int dy = d/3, dx = d%3;
        int qr = r + dy - 1, qc = c + dx - 1;
        if (qr >= 0 && qr < HH && qc >= 0 && qc < WW)
            acc += g_swsum[d]*g_gated[qr*WW + qc] + g_gconst[d];
    }
    g_att[p] = 1.f/(1.f + expf(-acc));
}

// -------- mul band: out = img*att for band's pixel groups, img now L2-hot -------
#define MULBB (BAND_PG*16/256)     // 704 blocks per band
__global__ __launch_bounds__(256) void mul_band_kernel(const float* __restrict__ img,
                                                       float* __restrict__ out,
                                                       int pg_start)
{
    const int t  = blockIdx.x*256 + threadIdx.x;   // < BAND_PG*16
    const int pl = t % BAND_PG;
    const int c0 = t / BAND_PG;                    // 0..15
    const int pg = pg_start + pl;
    const float4 a = reinterpret_cast<const float4*>(g_att)[pg];
    const float4* img4 = reinterpret_cast<const float4*>(img);
    float4*       out4 = reinterpret_cast<float4*>(out);
#pragma unroll
    for (int k = 0; k < 16; k++) {
        size_t i = (size_t)(c0 + 16*k)*HWP4 + pg;
        float4 v = img4[i];
        v.x *= a.x; v.y *= a.y; v.z *= a.z; v.w *= a.w;
        __stcs(&out4[i], v);     // out never re-read: keep img band in L2
    }
}

extern "C" void kernel_launch(void* const* d_in, const int* in_sizes, int n_in,
                              void* d_out, int out_size)
{
    const float* img      = (const float*)d_in[0];
    const float* feat0    = (const float*)d_in[1];
    const float* coord0   = (const float*)d_in[2];
    const int*   grid0    = (const int*)  d_in[3];
    const float* feat1    = (const float*)d_in[4];
    const float* coord1   = (const float*)d_in[5];
    const int*   grid1    = (const int*)  d_in[6];
    const float* feat2    = (const float*)d_in[7];
    const float* coord2   = (const float*)d_in[8];
    const int*   grid2    = (const int*)  d_in[9];
    const float* rd0_w    = (const float*)d_in[10];
    const float* rd0_b    = (const float*)d_in[11];
    const float* rd1_w    = (const float*)d_in[12];
    const float* rd1_b    = (const float*)d_in[13];
    const float* rd2_w    = (const float*)d_in[14];
    const float* rd2_b    = (const float*)d_in[15];
    const float* rd3_w    = (const float*)d_in[16];
    const float* rd3_b    = (const float*)d_in[17];
    const float* sp_w     = (const float*)d_in[18];
    const float* sp_b     = (const float*)d_in[19];
    float* out = (float*)d_out;

    const int N0 = in_sizes[3] / 2;
    const int N1 = in_sizes[6] / 2;
    const int N2 = in_sizes[9] / 2;
    const int SB0 = (N0 + 127)/128;
    const int SB1 = (N1 + 127)/128;
    const int SB2 = (N2 + 127)/128;

    initA_kernel<<<ZB + (NTA + 7)/8, 256>>>(rd2_w, rd2_b, rd0_b, rd1_b, sp_w);
    initB_kernel<<<NBB + 1, 256>>>(rd0_w, rd1_w, sp_w);

    // band row ranges with +/-1 halo for gated
    for (int band = 0; band < NBANDS; band++) {
        const int r0 = band*RPB;
        const int hr0 = (r0 == 0) ? 0 : r0 - 1;
        const int hr1 = (r0 + RPB >= HH) ? HH : r0 + RPB + 1;
        const int p4s = hr0 * W4;
        const int p4e = hr1 * W4;
        const int gu  = (p4e - p4s + 63)/64;

        if (band == 0) {
            fused0_kernel<<<gu + SB0 + SB1 + SB2, 256>>>(
                img, rd3_w, rd3_b, gu, p4s, p4e,
                feat0, coord0, grid0, N0, SB0,
                feat1, coord1, grid1, N1, SB1,
                feat2, coord2, grid2, N2);
        } else {
            gated_band_kernel<<<gu, 256>>>(img, rd3_w, rd3_b, p4s, p4e);
        }
        attention_kernel<<<(RPB*WW)/256, 256>>>(sp_b, r0*WW);
        mul_band_kernel<<<MULBB, 256>>>(img, out, r0*W4);
    }
}

// round 14
// speedup vs baseline: 1.3152x; 1.3152x over previous
#include <cuda_runtime.h>
#include <math.h>

#define HH 256
#define WW 704
#define HWP (HH*WW)          // 180224
#define HWP4 (HWP/4)         // 45056
#define CIMG 256
#define GUNITS (HWP4/64)     // 704 gated units, 64 float4 pixels each

// ---------------- scratch (static device globals; no allocation) ----------------
__device__ __align__(16) float g_gated[HWP];
__device__ __align__(16) float g_L[HWP];
__device__ __align__(16) float g_att[HWP];
__device__ float g_t[9*131];
__device__ float g_swsum[9];
__device__ float g_gconst[9];
__device__ float g_const2[131];
__device__ __align__(16) float4 g_M4_0[9*8];    // FC=32
__device__ __align__(16) float4 g_M4_1[9*16];   // FC=64
__device__ __align__(16) float4 g_M4_2[9*32];   // FC=128
__device__ float g_C0[27], g_C1[27], g_C2[27];  // [d][3] coord weights

__device__ __forceinline__ float warp_red(float s) {
#pragma unroll
    for (int o = 16; o > 0; o >>= 1) s += __shfl_xor_sync(0xffffffffu, s, o);
    return s;
}

// ---------------- initA: zero L (176 float4 blocks) + warp-dot tasks ------------
#define ZB 176
#define NTA 1319
__global__ __launch_bounds__(256) void initA_kernel(
    const float* __restrict__ W2, const float* __restrict__ b2,
    const float* __restrict__ b0, const float* __restrict__ b1,
    const float* __restrict__ spw)
{
    int b = blockIdx.x;
    if (b < ZB) {
        reinterpret_cast<float4*>(g_L)[b*256 + threadIdx.x] = make_float4(0.f,0.f,0.f,0.f);
        return;
    }
    int task = (b - ZB)*8 + (threadIdx.x >> 5);
    int lane = threadIdx.x & 31;
    if (task >= NTA) return;

    if (task < 131) {
        int c = task;
        float s = 0.f;
        for (int k = lane; k < 131; k += 32) s += W2[c*131+k]*(b0[k]+b1[k]);
        s = warp_red(s);
        if (lane == 0) g_const2[c] = s + b2[c];
    } else if (task < 140) {
        int d = task - 131;
        float s = 0.f;
        for (int c = lane; c < 131; c += 32) s += spw[c*9+d];
        s = warp_red(s);
        if (lane == 0) g_swsum[d] = s;
    } else {
        int idx = task - 140;
        int d = idx / 131, k = idx - d*131;
        float s = 0.f;
        for (int c = lane; c < 131; c += 32) s += spw[c*9+d]*W2[c*131+k];
        s = warp_red(s);
        if (lane == 0) g_t[idx] = s;
    }
}

// ---------------- initB: gconst + M0/M1 (packed) + pack t -----------------------
#define NTB 927
#define NBB ((NTB + 7)/8)       // 116
__global__ __launch_bounds__(256) void initB_kernel(
    const float* __restrict__ W0, const float* __restrict__ W1,
    const float* __restrict__ spw)
{
    int b = blockIdx.x;
    if (b == NBB) {  // pack t -> M4_2 / C2
        for (int i = threadIdx.x; i < 9*131; i += 256) {
            int d = i / 131, j = i - d*131;
            float v = g_t[i];
            if (j < 128) reinterpret_cast<float*>(g_M4_2)[d*128 + j] = v;
            else         g_C2[d*3 + (j - 128)] = v;
        }
        return;
    }
    int task = b*8 + (threadIdx.x >> 5);
    int lane = threadIdx.x & 31;
    if (task >= NTB) return;

    if (task < 9) {
        int d = task;
        float s = 0.f;
        for (int c = lane; c < 131; c += 32) s += spw[c*9+d]*g_const2[c];
        s = warp_red(s);
        if (lane == 0) g_gconst[d] = s;
    } else if (task < 324) {
        int idx = task - 9;
        int d = idx / 35, j = idx - d*35;
        float s = 0.f;
        for (int k = lane; k < 131; k += 32) s += g_t[d*131+k]*W0[k*35+j];
        s = warp_red(s);
        if (lane == 0) {
            if (j < 32) reinterpret_cast<float*>(g_M4_0)[d*32 + j] = s;
            else        g_C0[d*3 + (j - 32)] = s;
        }
    } else {
        int idx = task - 324;
        int d = idx / 67, j = idx - d*67;
        float s = 0.f;
        for (int k = lane; k < 131; k += 32) s += g_t[d*131+k]*W1[k*67+j];
        s = warp_red(s);
        if (lane == 0) {
            if (j < 64) reinterpret_cast<float*>(g_M4_1)[d*64 + j] = s;
            else        g_C1[d*3 + (j - 64)] = s;
        }
    }
}

// -------- quad-split scatter: 4 lanes per point, 128 points per block (2x64) ----
template<int FC>
__device__ __forceinline__ void scatter_body(const float* __restrict__ feat,
                                             const float* __restrict__ coord,
                                             const int*   __restrict__ grid,
                                             int N, const float4* __restrict__ M4g,
                                             const float* __restrict__ Cg, int blk,
                                             float4* sM4, float* sC)
{
    constexpr int K4 = FC/4;
    constexpr int IT = K4/4;
    const int tid = threadIdx.x;
    for (int i = tid; i < 9*K4; i += 256) sM4[i] = M4g[i];
    if (tid < 27) sC[tid] = Cg[tid];
    __syncthreads();

    const int lane = tid & 31;
    const int q    = lane >> 2;
    const int l    = lane & 3;

#pragma unroll
    for (int half = 0; half < 2; half++) {
        const int pt = blk*128 + half*64 + (tid >> 5)*8 + q;
        const bool valid = pt < N;

        float acc[9];
#pragma unroll
        for (int d = 0; d < 9; d++) acc[d] = 0.f;

        if (valid) {
            const float4* xf = reinterpret_cast<const float4*>(feat) + (size_t)pt*K4;
#pragma unroll
            for (int it = 0; it < IT; it++) {
                float4 x = xf[l + 4*it];
#pragma unroll
                for (int d = 0; d < 9; d++) {
                    float4 m = sM4[d*K4 + l + 4*it];
                    acc[d] += m.x*x.x + m.y*x.y + m.z*x.z + m.w*x.w;
                }
            }
        }
#pragma unroll
        for (int d = 0; d < 9; d++) {
            acc[d] += __shfl_xor_sync(0xffffffffu, acc[d], 1);
            acc[d] += __shfl_xor_sync(0xffffffffu, acc[d], 2);
        }
        if (valid && l == 0) {
            float c0 = coord[3*(size_t)pt+0], c1 = coord[3*(size_t)pt+1], c2 = coord[3*(size_t)pt+2];
            const int gx = grid[2*pt+0];
            const int gy = grid[2*pt+1];
#pragma unroll
            for (int d = 0; d < 9; d++) {
                float v = acc[d] + sC[d*3+0]*c0 + sC[d*3+1]*c1 + sC[d*3+2]*c2;
                int dy = d/3, dx = d - 3*dy;
                int pr = gy + 1 - dy, pc = gx + 1 - dx;
                if (pr >= 0 && pr < HH && pc >= 0 && pc < WW)
                    atomicAdd(&g_L[pr*WW + pc], v);
            }
        }
    }
}

// -------- fused kernel: gated/scatter blocks PROPORTIONALLY INTERLEAVED ---------
// block b is gated iff floor((b+1)*GU/TOT) > floor(b*GU/TOT); unit = floor(b*GU/TOT)
__global__ __launch_bounds__(256, 8) void fused_kernel(
    const float* __restrict__ img, const float* __restrict__ w3, const float* __restrict__ b3,
    int TOT,
    const float* __restrict__ f0, const float* __restrict__ c0, const int* __restrict__ gr0, int N0, int SB0,
    const float* __restrict__ f1, const float* __restrict__ c1, const int* __restrict__ gr1, int N1, int SB1,
    const float* __restrict__ f2, const float* __restrict__ c2, const int* __restrict__ gr2, int N2)
{
    __shared__ float  sw[CIMG];
    __shared__ float4 sPart[256];
    __shared__ float4 sM4[9*32];
    __shared__ float  sC[27];
    const int tid = threadIdx.x;
    const int b   = blockIdx.x;

    const int gBefore  = (int)(((long long)b     * GUNITS) / TOT);
    const int gBefore1 = (int)(((long long)(b+1) * GUNITS) / TOT);

    if (gBefore1 > gBefore) {
        // ---- gated unit = 64 float4 pixels, 4-way channel split ----
        const int u = gBefore;
        for (int i = tid; i < CIMG; i += 256) sw[i] = w3[i];
        __syncthreads();
        const int f  = tid & 63;
        const int qq = tid >> 6;
        const int p4 = u*64 + f;
        const float4* img4 = reinterpret_cast<const float4*>(img);
        float4 a0 = make_float4(0.f,0.f,0.f,0.f);
        float4 a1 = make_float4(0.f,0.f,0.f,0.f);
        const int cbase = qq*64;
#pragma unroll 8
        for (int c = cbase; c < cbase + 64; c += 2) {
            float4 v0 = img4[(size_t)c*HWP4 + p4];
            float4 v1 = img4[(size_t)(c+1)*HWP4 + p4];
            float w0 = sw[c], w1 = sw[c+1];
            a0.x += w0*v0.x; a0.y += w0*v0.y; a0.z += w0*v0.z; a0.w += w0*v0.w;
            a1.x += w1*v1.x; a1.y += w1*v1.y; a1.z += w1*v1.z; a1.w += w1*v1.w;
        }
        a0.x += a1.x; a0.y += a1.y; a0.z += a1.z; a0.w += a1.w;
        sPart[tid] = a0;
        __syncthreads();
        if (tid < 64) {
            float4 r0 = sPart[tid], r1 = sPart[tid+64], r2 = sPart[tid+128], r3 = sPart[tid+192];
            float bb = __ldg(b3);
            float4 r = make_float4(bb + r0.x + r1.x + r2.x + r3.x,
                                   bb + r0.y + r1.y + r2.y + r3.y,
                                   bb + r0.z + r1.z + r2.z + r3.z,
                                   bb + r0.w + r1.w + r2.w + r3.w);
            reinterpret_cast<float4*>(g_gated)[p4] = r;
        }
        return;
    }

    // ---- scatter block ----
    int sb = b - gBefore;          // scatter index among non-gated blocks
    if (sb < SB0) { scatter_body<32>(f0, c0, gr0, N0, g_M4_0, g_C0, sb, sM4, sC); return; }
    sb -= SB0;
    if (sb < SB1) { scatter_body<64>(f1, c1, gr1, N1, g_M4_1, g_C1, sb, sM4, sC); return; }
    sb -= SB1;
    scatter_body<128>(f2, c2, gr2, N2, g_M4_2, g_C2, sb, sM4, sC);
}

// ---------------- attention: sigmoid(spb + L + taps(gated) + consts) ------------
__global__ __launch_bounds__(256) void attention_kernel(const float* __restrict__ spb)
{
    int p = blockIdx.x*256 + threadIdx.x;
    int r = p / WW, c = p - r*WW;
    float acc = __ldg(spb) + g_L[p];
#pragma unroll
    for (int d = 0; d < 9; d++) {
        int dy = d/3, dx = d%3;
        int qr = r + dy - 1, qc = c + dx - 1;
        if (qr >= 0 && qr < HH && qc >= 0 && qc < WW)
            acc += g_swsum[d]*g_gated[qr*WW + qc] + g_gconst[d];
    }
    g_att[p] = 1.f/(1.f + expf(-acc));
}

// ------ mul: out = img * att, REVERSED block order; __stcs on stores ------------
#define MULB (HWP4*16/256)      // 2816 blocks
__global__ __launch_bounds__(256) void mul_kernel(const float* __restrict__ img,
                                                  float* __restrict__ out)
{
    const int bb = (int)gridDim.x - 1 - (int)blockIdx.x;
    const int t  = bb*256 + threadIdx.x;
    const int pg = t % HWP4;
    const int c0 = t / HWP4;
    const float4 a = reinterpret_cast<const float4*>(g_att)[pg];
    const float4* img4 = reinterpret_cast<const float4*>(img);
    float4*       out4 = reinterpret_cast<float4*>(out);
#pragma unroll
    for (int k = 0; k < 16; k++) {
        size_t i = (size_t)(c0 + 16*k)*HWP4 + pg;
        float4 v = img4[i];
        v.x *= a.x; v.y *= a.y; v.z *= a.z; v.w *= a.w;
        __stcs(&out4[i], v);
    }
}

extern "C" void kernel_launch(void* const* d_in, const int* in_sizes, int n_in,
                              void* d_out, int out_size)
{
    const float* img      = (const float*)d_in[0];
    const float* feat0    = (const float*)d_in[1];
    const float* coord0   = (const float*)d_in[2];
    const int*   grid0    = (const int*)  d_in[3];
    const float* feat1    = (const float*)d_in[4];
    const float* coord1   = (const float*)d_in[5];
    const int*   grid1    = (const int*)  d_in[6];
    const float* feat2    = (const float*)d_in[7];
    const float* coord2   = (const float*)d_in[8];
    const int*   grid2    = (const int*)  d_in[9];
    const float* rd0_w    = (const float*)d_in[10];
    const float* rd0_b    = (const float*)d_in[11];
    const float* rd1_w    = (const float*)d_in[12];
    const float* rd1_b    = (const float*)d_in[13];
    const float* rd2_w    = (const float*)d_in[14];
    const float* rd2_b    = (const float*)d_in[15];
    const float* rd3_w    = (const float*)d_in[16];
    const float* rd3_b    = (const float*)d_in[17];
    const float* sp_w     = (const float*)d_in[18];
    const float* sp_b     = (const float*)d_in[19];
    float* out = (float*)d_out;

    const int N0 = in_sizes[3] / 2;
    const int N1 = in_sizes[6] / 2;
    const int N2 = in_sizes[9] / 2;
    const int SB0 = (N0 + 127)/128;
    const int SB1 = (N1 + 127)/128;
    const int SB2 = (N2 + 127)/128;
    const int TOT = GUNITS + SB0 + SB1 + SB2;

    initA_kernel<<<ZB + (NTA + 7)/8, 256>>>(rd2_w, rd2_b, rd0_b, rd1_b, sp_w);
    initB_kernel<<<NBB + 1, 256>>>(rd0_w, rd1_w, sp_w);

    fused_kernel<<<TOT, 256>>>(
        img, rd3_w, rd3_b, TOT,
        feat0, coord0, grid0, N0, SB0,
        feat1, coord1, grid1, N1, SB1,
        feat2, coord2, grid2, N2);

    attention_kernel<<<HWP/256, 256>>>(sp_b);
    mul_kernel<<<MULB, 256>>>(img, out);
}